// round 5
// baseline (speedup 1.0000x reference)
#include <cuda_runtime.h>
#include <math.h>
#include <stdint.h>

#define Bn 8
#define Sn 2048
#define Dn 128
#define Ln 3
#define BS (Bn*Sn)          // 16384 rows
#define CHK 64
#define NCH (Sn/CHK)        // 32
#define NCHUNK (Bn*NCH)     // 256
#define SCALEF 0.08838834764831845f
#define RSTRIDE 33          // padded smem row stride in float4

// gemm_tc smem layout (floats)
#define APITCH 36           // 32 k + pad (36%32==4 -> conflict-free A frags)
#define BPITCH 136          // 128 n + pad (136%32==8 -> conflict-free B frags)
#define ASZ (128*APITCH)    // 4608
#define BSZ (32*BPITCH)     // 4352
#define OFF_AL ASZ
#define OFF_BH (2*ASZ)
#define OFF_BL (2*ASZ + BSZ)
#define OFF_RED (2*ASZ + 2*BSZ)
#define SMEM_FLOATS (OFF_RED + 256)
#define SMEM_BYTES (SMEM_FLOATS*4)   // 72704

// ---------------- static device scratch ----------------
__device__ float g_G[Ln*Dn*Dn];
__device__ float g_u[Ln*Dn];
__device__ float g_v[Ln*Dn];
__device__ float g_beta[Ln];
__device__ float g_HG[Ln*BS*Dn];
__device__ float g_theta[Ln*BS];
__device__ float g_phi[Ln*BS];
__device__ float g_a[Ln*BS];
__device__ float g_c[Ln*BS];
__device__ float g_Z[BS];
__device__ float g_LDJ[BS];
__device__ float g_U[NCHUNK*Dn];
__device__ float g_Cex[NCHUNK*Dn];
__device__ float g_sig[NCHUNK];
__device__ float g_gam[NCHUNK];
__device__ float g_sigex[NCHUNK];
__device__ float g_gamex[NCHUNK];

// ---------------- helpers ----------------
__device__ __forceinline__ void split_tf32(float x, float& hi, float& lo) {
    uint32_t h;
    asm("cvt.rna.tf32.f32 %0, %1;" : "=r"(h) : "f"(x));
    hi = __uint_as_float(h);
    float r = x - hi;
    uint32_t l2;
    asm("cvt.rna.tf32.f32 %0, %1;" : "=r"(l2) : "f"(r));
    lo = __uint_as_float(l2);
}

#define MMA_TF32(c, a, b) \
    asm volatile("mma.sync.aligned.m16n8k8.row.col.f32.tf32.tf32.f32 " \
        "{%0,%1,%2,%3},{%4,%5,%6,%7},{%8,%9},{%0,%1,%2,%3};" \
        : "+f"((c)[0]), "+f"((c)[1]), "+f"((c)[2]), "+f"((c)[3]) \
        : "r"((a)[0]), "r"((a)[1]), "r"((a)[2]), "r"((a)[3]), \
          "r"((b)[0]), "r"((b)[1]))

// ---------------- P0: G = Wq Wk^T, u, v, beta ----------------
__global__ void prep_G(const float* __restrict__ Wq, const float* __restrict__ Wk,
                       const float* __restrict__ bq, const float* __restrict__ bk) {
    int l = blockIdx.x;
    int drow = blockIdx.y;
    int e = threadIdx.x;            // 128 threads
    __shared__ float wq[Dn];
    wq[e] = Wq[l*Dn*Dn + drow*Dn + e];
    __syncthreads();
    const float* wkrow = Wk + l*Dn*Dn + e*Dn;
    float acc = 0.f;
    #pragma unroll 8
    for (int j = 0; j < Dn; j++) acc += wq[j] * wkrow[j];
    g_G[l*Dn*Dn + drow*Dn + e] = acc;
    if (e == 0) {
        float s = 0.f;
        const float* bkl = bk + l*Dn;
        for (int j = 0; j < Dn; j++) s += wq[j] * bkl[j];
        g_u[l*Dn + drow] = s;
    }
    if (drow == 0) {
        float s = 0.f;
        const float* bql = bq + l*Dn;
        for (int j = 0; j < Dn; j++) s += wkrow[j] * bql[j];
        g_v[l*Dn + e] = s;
        if (e == 0) {
            float sb = 0.f;
            for (int j = 0; j < Dn; j++) sb += bql[j] * bk[l*Dn + j];
            g_beta[l] = sb;
        }
    }
}

// ---------------- P1: fused per-row MVs + Z/LDJ init + layer-0 chunk sums ----------------
__global__ void __launch_bounds__(256) prep_chunk(
        const float* __restrict__ H, const float* __restrict__ Y,
        const float* __restrict__ MQ, const float* __restrict__ wi,
        const float* __restrict__ bi) {
    __shared__ __align__(16) float4 Hs4[CHK*RSTRIDE];
    __shared__ __align__(16) float sw[7*Dn];
    __shared__ float zsh[CHK], csh0[CHK];
    int blk = blockIdx.x;            // 256 chunks
    int base = blk * CHK;
    int tid = threadIdx.x;

    for (int i = tid; i < 7*Dn; i += 256)
        sw[i] = (i < Dn) ? wi[i] : (i < 4*Dn ? g_u[i-Dn] : g_v[i-4*Dn]);
    const float4* Hg4 = (const float4*)(H + (size_t)base*Dn);
    for (int i = tid; i < CHK*32; i += 256)
        Hs4[(i>>5)*RSTRIDE + (i&31)] = Hg4[i];
    __syncthreads();

    int r = tid >> 2, p = tid & 3;
    const float4* hrow = Hs4 + r*RSTRIDE + p;
    const float4* swp = ((const float4*)sw) + p;
    float acc[7];
    #pragma unroll
    for (int k = 0; k < 7; k++) acc[k] = 0.f;
    #pragma unroll
    for (int q = 0; q < 8; q++) {
        float4 h = hrow[q*4];
        #pragma unroll
        for (int k = 0; k < 7; k++) {
            float4 w = swp[k*32 + q*4];
            acc[k] += h.x*w.x + h.y*w.y + h.z*w.z + h.w*w.w;
        }
    }
    #pragma unroll
    for (int k = 0; k < 7; k++) {
        acc[k] += __shfl_xor_sync(0xffffffffu, acc[k], 1);
        acc[k] += __shfl_xor_sync(0xffffffffu, acc[k], 2);
    }
    int row = base + r;
    if (p == 0) {
        float el0 = acc[0] + bi[0];
        float y = Y[row], mq = MQ[row];
        float z = (y*mq - el0) * mq;
        g_Z[row] = z; zsh[r] = z;
        g_LDJ[row] = 1.0f;
        #pragma unroll
        for (int l = 0; l < Ln; l++) {
            g_a[l*BS + row] = acc[1+l];
            g_c[l*BS + row] = acc[4+l];
        }
        csh0[r] = acc[4];
    }
    __syncthreads();
    const float* Hsf = (const float*)Hs4;
    if (tid < Dn) {
        float a = 0.f;
        #pragma unroll 8
        for (int t = 0; t < CHK; t++) a += Hsf[t*(RSTRIDE*4) + tid] * zsh[t];
        g_U[blk*Dn + tid] = a;
    }
    if (tid == 255) {
        float s = 0.f, g = 0.f;
        for (int t = 0; t < CHK; t++) { s += zsh[t]; g += csh0[t]*zsh[t]; }
        g_sig[blk] = s; g_gam[blk] = g;
    }
}

// ---------------- P2: tensor-core tf32 4-pass (fp32-exact) projection GEMM ----------------
// grid (BS/128, 9); 128 threads; warp tile 64x64; K in 4 slices of 32
__global__ void __launch_bounds__(128, 2) gemm_tc(
    const float* __restrict__ H,
    const float* __restrict__ tW1, const float* __restrict__ tb1,
    const float* __restrict__ tW2, const float* __restrict__ tb2,
    const float* __restrict__ pW1, const float* __restrict__ pb1,
    const float* __restrict__ pW2, const float* __restrict__ pb2) {

    extern __shared__ float smem[];
    float* sAh = smem;
    float* sAl = smem + OFF_AL;
    float* sBh = smem + OFF_BH;
    float* sBl = smem + OFF_BL;
    float* red = smem + OFF_RED;

    int w = blockIdx.y;
    int l = w / 3, kind = w - l*3;
    const float* Wmat;
    const float* bia1 = nullptr;
    if (kind == 0)      { Wmat = g_G + l*Dn*Dn; }
    else if (kind == 1) { Wmat = tW1 + l*Dn*Dn; bia1 = tb1 + l*Dn; }
    else                { Wmat = pW1 + l*Dn*Dn; bia1 = pb1 + l*Dn; }

    int m0 = blockIdx.x * 128;
    int tid = threadIdx.x;
    int lane = tid & 31, wid = tid >> 5;
    int wm = wid >> 1, wn = wid & 1;
    int gid = lane >> 2, qid = lane & 3;

    float c[4][8][4];
    #pragma unroll
    for (int mi = 0; mi < 4; mi++)
        #pragma unroll
        for (int ni = 0; ni < 8; ni++)
            #pragma unroll
            for (int j = 0; j < 4; j++) c[mi][ni][j] = 0.f;

    const float4* H4 = (const float4*)H;
    const float4* W4 = (const float4*)Wmat;

    for (int s = 0; s < 4; s++) {
        __syncthreads();
        // load + split A slice: 128 rows x 32 k
        #pragma unroll
        for (int j = 0; j < 8; j++) {
            int i = tid + j*128;
            int row = i >> 3, kq = i & 7;
            float4 v = H4[(size_t)(m0 + row)*32 + s*8 + kq];
            float4 hi, lo;
            split_tf32(v.x, hi.x, lo.x);
            split_tf32(v.y, hi.y, lo.y);
            split_tf32(v.z, hi.z, lo.z);
            split_tf32(v.w, hi.w, lo.w);
            *(float4*)(sAh + row*APITCH + kq*4) = hi;
            *(float4*)(sAl + row*APITCH + kq*4) = lo;
        }
        // load + split B slice: 32 k x 128 n
        #pragma unroll
        for (int j = 0; j < 8; j++) {
            int i = tid + j*128;
            int k = i >> 5, nq = i & 31;
            float4 v = W4[(size_t)(s*32 + k)*32 + nq];
            float4 hi, lo;
            split_tf32(v.x, hi.x, lo.x);
            split_tf32(v.y, hi.y, lo.y);
            split_tf32(v.z, hi.z, lo.z);
            split_tf32(v.w, hi.w, lo.w);
            *(float4*)(sBh + k*BPITCH + nq*4) = hi;
            *(float4*)(sBl + k*BPITCH + nq*4) = lo;
        }
        __syncthreads();

        #pragma unroll
        for (int pass = 0; pass < 4; pass++) {
            const float* pA = (pass >= 2) ? sAl : sAh;
            const float* pB = (pass & 1)  ? sBl : sBh;
            #pragma unroll
            for (int ks = 0; ks < 32; ks += 8) {
                uint32_t af[4][4];
                #pragma unroll
                for (int mi = 0; mi < 4; mi++) {
                    int r = wm*64 + mi*16 + gid;
                    const float* base = pA + r*APITCH + ks + qid;
                    af[mi][0] = __float_as_uint(base[0]);
                    af[mi][1] = __float_as_uint(base[8*APITCH]);
                    af[mi][2] = __float_as_uint(base[4]);
                    af[mi][3] = __float_as_uint(base[8*APITCH + 4]);
                }
                uint32_t bf_[8][2];
                #pragma unroll
                for (int ni = 0; ni < 8; ni++) {
                    int n = wn*64 + ni*8 + gid;
                    const float* base = pB + (ks + qid)*BPITCH + n;
                    bf_[ni][0] = __float_as_uint(base[0]);
                    bf_[ni][1] = __float_as_uint(base[4*BPITCH]);
                }
                #pragma unroll
                for (int mi = 0; mi < 4; mi++)
                    #pragma unroll
                    for (int ni = 0; ni < 8; ni++)
                        MMA_TF32(c[mi][ni], af[mi], bf_[ni]);
            }
        }
    }

    if (kind == 0) {
        float* outp = g_HG + (size_t)l*BS*Dn;
        #pragma unroll
        for (int mi = 0; mi < 4; mi++) {
            int r = m0 + wm*64 + mi*16 + gid;
            #pragma unroll
            for (int ni = 0; ni < 8; ni++) {
                int ccol = wn*64 + ni*8 + qid*2;
                float* o = outp + (size_t)r*Dn + ccol;
                *(float2*)o = make_float2(c[mi][ni][0], c[mi][ni][1]);
                *(float2*)(o + 8*Dn) = make_float2(c[mi][ni][2], c[mi][ni][3]);
            }
        }
    } else {
        const float* W2 = (kind == 1 ? tW2 : pW2) + l*Dn;
        float bias2 = (kind == 1 ? tb2 : pb2)[l];
        float p[4][2];
        #pragma unroll
        for (int mi = 0; mi < 4; mi++) { p[mi][0] = 0.f; p[mi][1] = 0.f; }
        #pragma unroll
        for (int ni = 0; ni < 8; ni++) {
            int col0 = wn*64 + ni*8 + qid*2;
            float bb0 = bia1[col0], bb1 = bia1[col0+1];
            float w0 = W2[col0], w1 = W2[col0+1];
            #pragma unroll
            for (int mi = 0; mi < 4; mi++) {
                p[mi][0] += fmaxf(c[mi][ni][0] + bb0, 0.f)*w0
                          + fmaxf(c[mi][ni][1] + bb1, 0.f)*w1;
                p[mi][1] += fmaxf(c[mi][ni][2] + bb0, 0.f)*w0
                          + fmaxf(c[mi][ni][3] + bb1, 0.f)*w1;
            }
        }
        #pragma unroll
        for (int mi = 0; mi < 4; mi++) {
            #pragma unroll
            for (int hh = 0; hh < 2; hh++) {
                p[mi][hh] += __shfl_xor_sync(0xffffffffu, p[mi][hh], 1);
                p[mi][hh] += __shfl_xor_sync(0xffffffffu, p[mi][hh], 2);
            }
        }
        if (qid == 0) {
            #pragma unroll
            for (int mi = 0; mi < 4; mi++) {
                int r = wm*64 + mi*16 + gid;
                red[r*2 + wn]       = p[mi][0];
                red[(r+8)*2 + wn]   = p[mi][1];
            }
        }
        __syncthreads();
        float* outv = (kind == 1 ? g_theta : g_phi) + l*BS;
        float v = red[tid*2] + red[tid*2+1] + bias2;
        outv[m0 + tid] = (kind == 1) ? expf(tanhf(v)) : v;
    }
}

// ---------------- K2: exclusive chunk prefix (MLP-32, register-resident) ----------------
__global__ void __launch_bounds__(128) chunk_prefix() {
    int b = blockIdx.x;      // Bn
    int tid = threadIdx.x;   // 128
    float u[NCH];
    #pragma unroll
    for (int ch = 0; ch < NCH; ch++)
        u[ch] = g_U[(b*NCH + ch)*Dn + tid];
    float acc = 0.f;
    #pragma unroll
    for (int ch = 0; ch < NCH; ch++) {
        g_Cex[(b*NCH + ch)*Dn + tid] = acc;
        acc += u[ch];
    }
    if (tid < NCH) {
        float s = g_sig[b*NCH + tid];
        float g = g_gam[b*NCH + tid];
        float ss = s, gg = g;
        #pragma unroll
        for (int off = 1; off < 32; off <<= 1) {
            float t1 = __shfl_up_sync(0xffffffffu, ss, off);
            float t2 = __shfl_up_sync(0xffffffffu, gg, off);
            if (tid >= off) { ss += t1; gg += t2; }
        }
        g_sigex[b*NCH + tid] = ss - s;
        g_gamex[b*NCH + tid] = gg - g;
    }
}

// ---------------- K3: chunk apply, 2 rows/thread ----------------
__global__ void __launch_bounds__(128) chunk_apply(
        const float* __restrict__ H, const float* __restrict__ MQ,
        int l, int fuse_next, float* Zoutp, float* LDJoutp) {
    __shared__ __align__(16) float4 Hs4[CHK*RSTRIDE];
    __shared__ __align__(16) float cp[Dn];
    __shared__ float zsh[CHK], csh[CHK], cshn[CHK], zo_sh[CHK];
    int blk = blockIdx.x;
    int base = blk * CHK;
    int tid = threadIdx.x;               // 128

    const float4* Hg4 = (const float4*)(H + (size_t)base*Dn);
    for (int i = tid; i < CHK*32; i += 128)
        Hs4[(i>>5)*RSTRIDE + (i&31)] = Hg4[i];
    if (tid < CHK) {
        zsh[tid] = g_Z[base + tid];
        csh[tid] = g_c[l*BS + base + tid];
        cshn[tid] = fuse_next ? g_c[(l+1)*BS + base + tid] : 0.f;
    }
    cp[tid] = g_Cex[blk*Dn + tid];
    __syncthreads();

    int pr = tid >> 2, p = tid & 3;
    int r0 = 2*pr, r1 = 2*pr + 1;
    int row0 = base + r0, row1 = base + r1;

    float4 hg0[8], hg1[8];
    const float4* hgr0 = (const float4*)(g_HG + (size_t)l*BS*Dn + (size_t)row0*Dn) + p;
    const float4* hgr1 = (const float4*)(g_HG + (size_t)l*BS*Dn + (size_t)row1*Dn) + p;
    #pragma unroll
    for (int q = 0; q < 8; q++) { hg0[q] = hgr0[q*4]; hg1[q] = hgr1[q*4]; }

    float a0 = g_a[l*BS + row0], a1 = g_a[l*BS + row1];
    float beta = g_beta[l];

    float cr0 = 0.f, cr1 = 0.f;
    const float4* cp4 = ((const float4*)cp) + p;
    #pragma unroll
    for (int q = 0; q < 8; q++) {
        float4 c4 = cp4[q*4];
        cr0 += hg0[q].x*c4.x + hg0[q].y*c4.y + hg0[q].z*c4.z + hg0[q].w*c4.w;
        cr1 += hg1[q].x*c4.x + hg1[q].y*c4.y + hg1[q].z*c4.z + hg1[q].w*c4.w;
    }

    float ip0 = 0.f, ip1 = 0.f, ds0 = 0.f, ds1 = 0.f;
    float szl0 = 0.f, scz0 = 0.f, szl1 = 0.f, scz1 = 0.f;
    int tmax = (r1 | 15) + 1;
    for (int t = 0; t < tmax; t++) {
        const float4* ht = Hs4 + t*RSTRIDE + p;
        float d0 = 0.f, d1 = 0.f;
        #pragma unroll
        for (int q = 0; q < 8; q++) {
            float4 h = ht[q*4];
            d0 += hg0[q].x*h.x + hg0[q].y*h.y + hg0[q].z*h.z + hg0[q].w*h.w;
            d1 += hg1[q].x*h.x + hg1[q].y*h.y + hg1[q].z*h.z + hg1[q].w*h.w;
        }
        float zt = zsh[t];
        if (t < r0)       ip0 += d0 * zt;
        else if (t == r0) ds0 = d0;
        if (t < r1)       ip1 += d1 * zt;
        else if (t == r1) ds1 = d1;
        if (p == 0) {
            float ct = csh[t];
            if (t < r0) { szl0 += zt; scz0 += ct*zt; }
            if (t < r1) { szl1 += zt; scz1 += ct*zt; }
        }
    }
    #pragma unroll
    for (int off = 1; off <= 2; off <<= 1) {
        ip0 += __shfl_xor_sync(0xffffffffu, ip0, off);
        ip1 += __shfl_xor_sync(0xffffffffu, ip1, off);
        ds0 += __shfl_xor_sync(0xffffffffu, ds0, off);
        ds1 += __shfl_xor_sync(0xffffffffu, ds1, off);
        cr0 += __shfl_xor_sync(0xffffffffu, cr0, off);
        cr1 += __shfl_xor_sync(0xffffffffu, cr1, off);
    }

    if (p == 0) {
        float sigp = g_sigex[blk], gamp = g_gamex[blk];
        const float E = 2.718281828459045f;
        #pragma unroll
        for (int rr = 0; rr < 2; rr++) {
            int r    = rr ? r1   : r0;
            int row  = rr ? row1 : row0;
            float as = rr ? a1   : a0;
            float crx = rr ? cr1 : cr0;
            float ipx = rr ? ip1 : ip0;
            float dsx = rr ? ds1 : ds0;
            float szl = rr ? szl1 : szl0;
            float scz = rr ? scz1 : scz0;

            float selfsc = SCALEF * (dsx + as + csh[r] + beta);
            float sp   = fmaxf(selfsc, 0.f) + log1pf(expf(-fabsf(selfsc)));
            float diag = sp + 1e-3f;
            float y = SCALEF*(crx + as*sigp + gamp + beta*sigp)
                    + SCALEF*(ipx + as*szl + scz + beta*szl)
                    + diag * zsh[r];

            float mq = MQ[row];
            float ldj = g_LDJ[row] + logf(diag) * mq;
            float th = g_theta[l*BS + row], ph = g_phi[l*BS + row];
            float z = y * mq * th + ph;
            ldj += th * mq;

            float zo, sl;
            if (fabsf(z) > 5.0f) {
                zo = z + (z > 0.f ? 1.f : -1.f);
                sl = 0.f;
            } else {
                float sh = sinhf(z);
                zo = asinhf(E * sh);
                float t1 = 1.f + E * sh;
                sl = logf(E * coshf(z)) - logf(t1 * t1);
            }
            ldj += sl * mq;

            zo_sh[r] = zo;
            if (Zoutp) { Zoutp[row] = zo; LDJoutp[row] = ldj; }
            else       { g_Z[row] = zo;   g_LDJ[row] = ldj; }
        }
    }

    if (fuse_next) {
        __syncthreads();
        const float* Hsf = (const float*)Hs4;
        float acc2 = 0.f;
        #pragma unroll 8
        for (int t = 0; t < CHK; t++) acc2 += Hsf[t*(RSTRIDE*4) + tid] * zo_sh[t];
        g_U[blk*Dn + tid] = acc2;
        if (tid == 127) {
            float ssum = 0.f, gsum = 0.f;
            for (int t = 0; t < CHK; t++) { ssum += zo_sh[t]; gsum += cshn[t]*zo_sh[t]; }
            g_sig[blk] = ssum; g_gam[blk] = gsum;
        }
    }
}

// ---------------- launch ----------------
extern "C" void kernel_launch(void* const* d_in, const int* in_sizes, int n_in,
                              void* d_out, int out_size) {
    (void)in_sizes; (void)n_in; (void)out_size;
    const float* H   = (const float*)d_in[0];
    const float* Y   = (const float*)d_in[1];
    const float* MQ  = (const float*)d_in[2];
    const float* Wq  = (const float*)d_in[3];
    const float* bq  = (const float*)d_in[4];
    const float* Wk  = (const float*)d_in[5];
    const float* bk  = (const float*)d_in[6];
    const float* tW1 = (const float*)d_in[7];
    const float* tb1 = (const float*)d_in[8];
    const float* tW2 = (const float*)d_in[9];
    const float* tb2 = (const float*)d_in[10];
    const float* pW1 = (const float*)d_in[11];
    const float* pb1 = (const float*)d_in[12];
    const float* pW2 = (const float*)d_in[13];
    const float* pb2 = (const float*)d_in[14];
    const float* wi  = (const float*)d_in[15];
    const float* bi  = (const float*)d_in[16];
    float* out = (float*)d_out;

    cudaFuncSetAttribute(gemm_tc, cudaFuncAttributeMaxDynamicSharedMemorySize, SMEM_BYTES);

    prep_G<<<dim3(Ln, Dn), Dn>>>(Wq, Wk, bq, bk);
    prep_chunk<<<NCHUNK, 256>>>(H, Y, MQ, wi, bi);
    gemm_tc<<<dim3(BS/128, 9), 128, SMEM_BYTES>>>(H, tW1, tb1, tW2, tb2,
                                                  pW1, pb1, pW2, pb2);

    for (int l = 0; l < Ln; l++) {
        chunk_prefix<<<Bn, 128>>>();
        if (l < Ln - 1) {
            chunk_apply<<<NCHUNK, 128>>>(H, MQ, l, 1, nullptr, nullptr);
        } else {
            chunk_apply<<<NCHUNK, 128>>>(H, MQ, l, 0, out, out + BS);
        }
    }
}

// round 7
// speedup vs baseline: 1.1099x; 1.1099x over previous
#include <cuda_runtime.h>
#include <cuda_bf16.h>
#include <math.h>
#include <stdint.h>

#define Bn 8
#define Sn 2048
#define Dn 128
#define Ln 3
#define BS (Bn*Sn)          // 16384 rows
#define CHK 64
#define NCH (Sn/CHK)        // 32
#define NCHUNK (Bn*NCH)     // 256
#define NTILE (BS/128)      // 128 row tiles
#define SCALEF 0.08838834764831845f
#define RSTRIDE 33          // padded smem row stride in float4

// bf16 image: 128 rows x 128 k, 256B row pitch, 16B-granule XOR swizzle
#define IMG_BYTES 32768
#define IMG_ELEMS 16384
#define STAGE_BYTES 65536                 // A split + B split
#define GEMM_DYN_BYTES (3*STAGE_BYTES)    // 192 KB

// ---------------- static device scratch ----------------
__device__ float g_G[Ln*Dn*Dn];
__device__ float g_u[Ln*Dn];
__device__ float g_v[Ln*Dn];
__device__ float g_beta[Ln];
__device__ float g_HG[Ln*BS*Dn];
__device__ float g_theta[Ln*BS];
__device__ float g_phi[Ln*BS];
__device__ float g_a[Ln*BS];
__device__ float g_c[Ln*BS];
__device__ float g_Z[BS];
__device__ float g_LDJ[BS];
__device__ float g_U[NCHUNK*Dn];
__device__ float g_Cex[NCHUNK*Dn];
__device__ float g_sig[NCHUNK];
__device__ float g_gam[NCHUNK];
__device__ float g_sigex[NCHUNK];
__device__ float g_gamex[NCHUNK];
__device__ __align__(16) __nv_bfloat16 g_Abf[NTILE*3*IMG_ELEMS];  // 12.6 MB
__device__ __align__(16) __nv_bfloat16 g_Bbf[9*3*IMG_ELEMS];      // 884 KB

// ---------------- asm helpers ----------------
#define LDSM4(r0,r1,r2,r3, addr) \
    asm volatile("ldmatrix.sync.aligned.m8n8.x4.shared.b16 {%0,%1,%2,%3}, [%4];" \
        : "=r"(r0),"=r"(r1),"=r"(r2),"=r"(r3) : "r"(addr))

#define MMA_BF16(c, a, b) \
    asm volatile("mma.sync.aligned.m16n8k16.row.col.f32.bf16.bf16.f32 " \
        "{%0,%1,%2,%3},{%4,%5,%6,%7},{%8,%9},{%0,%1,%2,%3};" \
        : "+f"((c)[0]),"+f"((c)[1]),"+f"((c)[2]),"+f"((c)[3]) \
        : "r"((a)[0]),"r"((a)[1]),"r"((a)[2]),"r"((a)[3]), \
          "r"((b)[0]),"r"((b)[1]))

#define CP_ASYNC16(dst, src) \
    asm volatile("cp.async.cg.shared.global [%0], [%1], 16;" :: "r"(dst), "l"(src))
#define CP_COMMIT() asm volatile("cp.async.commit_group;" ::: "memory")
#define CP_WAIT(n)  asm volatile("cp.async.wait_group %0;" :: "n"(n) : "memory")

// ---------------- P0: G = Wq Wk^T, u, v, beta ----------------
__global__ void prep_G(const float* __restrict__ Wq, const float* __restrict__ Wk,
                       const float* __restrict__ bq, const float* __restrict__ bk) {
    int l = blockIdx.x;
    int drow = blockIdx.y;
    int e = threadIdx.x;            // 128 threads
    __shared__ float wq[Dn];
    wq[e] = Wq[l*Dn*Dn + drow*Dn + e];
    __syncthreads();
    const float* wkrow = Wk + l*Dn*Dn + e*Dn;
    float acc = 0.f;
    #pragma unroll 8
    for (int j = 0; j < Dn; j++) acc += wq[j] * wkrow[j];
    g_G[l*Dn*Dn + drow*Dn + e] = acc;
    if (e == 0) {
        float s = 0.f;
        const float* bkl = bk + l*Dn;
        for (int j = 0; j < Dn; j++) s += wq[j] * bkl[j];
        g_u[l*Dn + drow] = s;
    }
    if (drow == 0) {
        float s = 0.f;
        const float* bql = bq + l*Dn;
        for (int j = 0; j < Dn; j++) s += wkrow[j] * bql[j];
        g_v[l*Dn + e] = s;
        if (e == 0) {
            float sb = 0.f;
            for (int j = 0; j < Dn; j++) sb += bql[j] * bk[l*Dn + j];
            g_beta[l] = sb;
        }
    }
}

// ---------------- split helpers ----------------
__device__ __forceinline__ void bf3_split(float x, __nv_bfloat16& c0,
                                          __nv_bfloat16& c1, __nv_bfloat16& c2) {
    c0 = __float2bfloat16_rn(x);
    float r1 = x - __bfloat162float(c0);
    c1 = __float2bfloat16_rn(r1);
    float r2 = r1 - __bfloat162float(c1);
    c2 = __float2bfloat16_rn(r2);
}

// ldmatrix-friendly image: 256B row pitch, 16B granule XOR by (row&7)
__device__ __forceinline__ uint32_t img_off(int row, int g) {
    return (uint32_t)row*256u + (((uint32_t)g*16u) ^ (((uint32_t)row & 7u)*16u));
}

// ---------------- split_A: H -> 3x bf16 images per 128-row tile ----------------
__global__ void __launch_bounds__(256) split_A(const float* __restrict__ H) {
    int tile = blockIdx.x;
    int tid = threadIdx.x;
    char* basep = (char*)(g_Abf + (size_t)tile*3*IMG_ELEMS);
    for (int it = tid; it < 2048; it += 256) {
        int row = it >> 4, g = it & 15;   // granule = 8 k-elems
        const float4* src = (const float4*)(H + ((size_t)tile*128 + row)*Dn + g*8);
        float4 v0 = src[0], v1 = src[1];
        float x[8] = {v0.x,v0.y,v0.z,v0.w,v1.x,v1.y,v1.z,v1.w};
        __align__(16) __nv_bfloat16 b[3][8];
        #pragma unroll
        for (int e = 0; e < 8; e++) bf3_split(x[e], b[0][e], b[1][e], b[2][e]);
        uint32_t sw = img_off(row, g);
        #pragma unroll
        for (int s = 0; s < 3; s++)
            *(uint4*)(basep + s*IMG_BYTES + sw) = *(const uint4*)b[s];
    }
}

// ---------------- split_B: weights (as B[n][k]) -> 3x bf16 images ----------------
__global__ void __launch_bounds__(256) split_B(const float* __restrict__ tW1,
                                               const float* __restrict__ pW1) {
    int w = blockIdx.x;          // 0..8
    int l = w / 3, kind = w - l*3;
    const float* W = (kind == 0) ? g_G + l*Dn*Dn
                   : (kind == 1) ? tW1 + l*Dn*Dn : pW1 + l*Dn*Dn;
    int tid = threadIdx.x;
    char* basep = (char*)(g_Bbf + (size_t)w*3*IMG_ELEMS);
    for (int it = tid; it < 2048; it += 256) {
        int g = it >> 7, n = it & 127;     // coalesced over n
        __align__(16) __nv_bfloat16 b[3][8];
        #pragma unroll
        for (int e = 0; e < 8; e++) {
            float xx = W[(size_t)(g*8 + e)*Dn + n];   // B[n][k] = W[k][n]
            bf3_split(xx, b[0][e], b[1][e], b[2][e]);
        }
        uint32_t sw = img_off(n, g);
        #pragma unroll
        for (int s = 0; s < 3; s++)
            *(uint4*)(basep + s*IMG_BYTES + sw) = *(const uint4*)b[s];
    }
}

// ---------------- P1: fused per-row MVs + Z/LDJ init + layer-0 chunk sums ----------------
__global__ void __launch_bounds__(256) prep_chunk(
        const float* __restrict__ H, const float* __restrict__ Y,
        const float* __restrict__ MQ, const float* __restrict__ wi,
        const float* __restrict__ bi) {
    __shared__ __align__(16) float4 Hs4[CHK*RSTRIDE];
    __shared__ __align__(16) float sw[7*Dn];
    __shared__ float zsh[CHK], csh0[CHK];
    int blk = blockIdx.x;            // 256 chunks
    int base = blk * CHK;
    int tid = threadIdx.x;

    for (int i = tid; i < 7*Dn; i += 256)
        sw[i] = (i < Dn) ? wi[i] : (i < 4*Dn ? g_u[i-Dn] : g_v[i-4*Dn]);
    const float4* Hg4 = (const float4*)(H + (size_t)base*Dn);
    for (int i = tid; i < CHK*32; i += 256)
        Hs4[(i>>5)*RSTRIDE + (i&31)] = Hg4[i];
    __syncthreads();

    int r = tid >> 2, p = tid & 3;
    const float4* hrow = Hs4 + r*RSTRIDE + p;
    const float4* swp = ((const float4*)sw) + p;
    float acc[7];
    #pragma unroll
    for (int k = 0; k < 7; k++) acc[k] = 0.f;
    #pragma unroll
    for (int q = 0; q < 8; q++) {
        float4 h = hrow[q*4];
        #pragma unroll
        for (int k = 0; k < 7; k++) {
            float4 w = swp[k*32 + q*4];
            acc[k] += h.x*w.x + h.y*w.y + h.z*w.z + h.w*w.w;
        }
    }
    #pragma unroll
    for (int k = 0; k < 7; k++) {
        acc[k] += __shfl_xor_sync(0xffffffffu, acc[k], 1);
        acc[k] += __shfl_xor_sync(0xffffffffu, acc[k], 2);
    }
    int row = base + r;
    if (p == 0) {
        float el0 = acc[0] + bi[0];
        float y = Y[row], mq = MQ[row];
        float z = (y*mq - el0) * mq;
        g_Z[row] = z; zsh[r] = z;
        g_LDJ[row] = 1.0f;
        #pragma unroll
        for (int l = 0; l < Ln; l++) {
            g_a[l*BS + row] = acc[1+l];
            g_c[l*BS + row] = acc[4+l];
        }
        csh0[r] = acc[4];
    }
    __syncthreads();
    const float* Hsf = (const float*)Hs4;
    if (tid < Dn) {
        float a = 0.f;
        #pragma unroll 8
        for (int t = 0; t < CHK; t++) a += Hsf[t*(RSTRIDE*4) + tid] * zsh[t];
        g_U[blk*Dn + tid] = a;
    }
    if (tid == 255) {
        float s = 0.f, g = 0.f;
        for (int t = 0; t < CHK; t++) { s += zsh[t]; g += csh0[t]*zsh[t]; }
        g_sig[blk] = s; g_gam[blk] = g;
    }
}

// ---------------- P2: bf16x3 6-pass HMMA projection GEMM ----------------
// grid (NTILE, 9); 256 threads; warp tile 32x64; cp.async staged operands
__global__ void __launch_bounds__(256, 1) gemm_mma(
        const float* __restrict__ tb1, const float* __restrict__ tW2,
        const float* __restrict__ tb2, const float* __restrict__ pb1,
        const float* __restrict__ pW2, const float* __restrict__ pb2) {

    extern __shared__ __align__(16) char dynsm[];
    __shared__ float red[256];
    __shared__ float s_b1[128], s_w2[128];

    int tile = blockIdx.x, w = blockIdx.y;
    int l = w / 3, kind = w - l*3;
    int tid = threadIdx.x, lane = tid & 31, wid = tid >> 5;
    int wm = wid >> 1, wn = wid & 1;           // 4 x 2 warp grid
    int gid = lane >> 2, qid = lane & 3;

    uint32_t sbase = (uint32_t)__cvta_generic_to_shared(dynsm);

    // stage copies: stage s = [A split s 32KB | B split s 32KB]
    const char* srcA = (const char*)(g_Abf + (size_t)tile*3*IMG_ELEMS);
    const char* srcB = (const char*)(g_Bbf + (size_t)w*3*IMG_ELEMS);
    #pragma unroll
    for (int s = 0; s < 3; s++) {
        for (int i = tid; i < 4096; i += 256) {
            uint32_t dst = sbase + s*STAGE_BYTES + i*16;
            const char* src = (i < 2048) ? (srcA + s*IMG_BYTES + i*16)
                                         : (srcB + s*IMG_BYTES + (i-2048)*16);
            CP_ASYNC16(dst, src);
        }
        CP_COMMIT();
    }

    if (kind != 0 && tid < 128) {
        s_b1[tid] = ((kind == 1 ? tb1 : pb1) + l*Dn)[tid];
        s_w2[tid] = ((kind == 1 ? tW2 : pW2) + l*Dn)[tid];
    }

    // per-lane fragment address components
    uint32_t sw_l   = (lane & 7) * 16;
    uint32_t koffA  = (lane & 16);
    uint32_t koffB  = (lane & 8) << 1;
    uint32_t n_l    = (lane & 7) + ((lane & 16) >> 1);
    uint32_t a_mbase[2], b_nbase[4];
    #pragma unroll
    for (int mi = 0; mi < 2; mi++)
        a_mbase[mi] = (wm*32 + mi*16 + (lane & 15)) * 256;
    #pragma unroll
    for (int nbi = 0; nbi < 4; nbi++)
        b_nbase[nbi] = (wn*64 + nbi*16 + n_l) * 256;

    float c[2][8][4];
    #pragma unroll
    for (int mi = 0; mi < 2; mi++)
        #pragma unroll
        for (int ni = 0; ni < 8; ni++)
            #pragma unroll
            for (int j = 0; j < 4; j++) c[mi][ni][j] = 0.f;

    const int pi[6] = {0, 0, 1, 1, 0, 2};
    const int pj[6] = {0, 1, 0, 1, 2, 0};
    #pragma unroll
    for (int p = 0; p < 6; p++) {
        if (p == 0)      { CP_WAIT(2); __syncthreads(); }
        else if (p == 1) { CP_WAIT(1); __syncthreads(); }
        else if (p == 4) { CP_WAIT(0); __syncthreads(); }
        uint32_t aS = sbase + pi[p]*STAGE_BYTES;
        uint32_t bS = sbase + pj[p]*STAGE_BYTES + IMG_BYTES;
        #pragma unroll
        for (int kk = 0; kk < 8; kk++) {
            uint32_t af[2][4];
            #pragma unroll
            for (int mi = 0; mi < 2; mi++)
                LDSM4(af[mi][0], af[mi][1], af[mi][2], af[mi][3],
                      aS + a_mbase[mi] + ((kk*32u + koffA) ^ sw_l));
            uint32_t bf[8][2];
            #pragma unroll
            for (int nbi = 0; nbi < 4; nbi++)
                LDSM4(bf[2*nbi][0], bf[2*nbi][1], bf[2*nbi+1][0], bf[2*nbi+1][1],
                      bS + b_nbase[nbi] + ((kk*32u + koffB) ^ sw_l));
            #pragma unroll
            for (int mi = 0; mi < 2; mi++)
                #pragma unroll
                for (int ni = 0; ni < 8; ni++)
                    MMA_BF16(c[mi][ni], af[mi], bf[ni]);
        }
    }

    if (kind == 0) {
        float* outp = g_HG + (size_t)l*BS*Dn;
        #pragma unroll
        for (int mi = 0; mi < 2; mi++) {
            int r0 = tile*128 + wm*32 + mi*16 + gid;
            #pragma unroll
            for (int ni = 0; ni < 8; ni++) {
                int col = wn*64 + ni*8 + qid*2;
                *(float2*)(outp + (size_t)r0*Dn + col) =
                    make_float2(c[mi][ni][0], c[mi][ni][1]);
                *(float2*)(outp + (size_t)(r0+8)*Dn + col) =
                    make_float2(c[mi][ni][2], c[mi][ni][3]);
            }
        }
    } else {
        float pr[2][2] = {{0.f,0.f},{0.f,0.f}};
        #pragma unroll
        for (int ni = 0; ni < 8; ni++) {
            int col = wn*64 + ni*8 + qid*2;
            float b1a = s_b1[col], b1b = s_b1[col+1];
            float w2a = s_w2[col], w2b = s_w2[col+1];
            #pragma unroll
            for (int mi = 0; mi < 2; mi++) {
                pr[mi][0] += fmaxf(c[mi][ni][0]+b1a,0.f)*w2a
                           + fmaxf(c[mi][ni][1]+b1b,0.f)*w2b;
                pr[mi][1] += fmaxf(c[mi][ni][2]+b1a,0.f)*w2a
                           + fmaxf(c[mi][ni][3]+b1b,0.f)*w2b;
            }
        }
        #pragma unroll
        for (int mi = 0; mi < 2; mi++)
            #pragma unroll
            for (int hh = 0; hh < 2; hh++) {
                pr[mi][hh] += __shfl_xor_sync(0xffffffffu, pr[mi][hh], 1);
                pr[mi][hh] += __shfl_xor_sync(0xffffffffu, pr[mi][hh], 2);
            }
        if (qid == 0) {
            #pragma unroll
            for (int mi = 0; mi < 2; mi++)
                #pragma unroll
                for (int hh = 0; hh < 2; hh++)
                    red[(wm*32 + mi*16 + hh*8 + gid)*2 + wn] = pr[mi][hh];
        }
        __syncthreads();
        if (tid < 128) {
            float v = red[tid*2] + red[tid*2+1] + (kind == 1 ? tb2 : pb2)[l];
            float* outv = (kind == 1 ? g_theta : g_phi) + l*BS;
            outv[tile*128 + tid] = (kind == 1) ? expf(tanhf(v)) : v;
        }
    }
}

// ---------------- K2: exclusive chunk prefix ----------------
__global__ void __launch_bounds__(128) chunk_prefix() {
    int b = blockIdx.x;      // Bn
    int tid = threadIdx.x;   // 128
    float u[NCH];
    #pragma unroll
    for (int ch = 0; ch < NCH; ch++)
        u[ch] = g_U[(b*NCH + ch)*Dn + tid];
    float acc = 0.f;
    #pragma unroll
    for (int ch = 0; ch < NCH; ch++) {
        g_Cex[(b*NCH + ch)*Dn + tid] = acc;
        acc += u[ch];
    }
    if (tid < NCH) {
        float s = g_sig[b*NCH + tid];
        float g = g_gam[b*NCH + tid];
        float ss = s, gg = g;
        #pragma unroll
        for (int off = 1; off < 32; off <<= 1) {
            float t1 = __shfl_up_sync(0xffffffffu, ss, off);
            float t2 = __shfl_up_sync(0xffffffffu, gg, off);
            if (tid >= off) { ss += t1; gg += t2; }
        }
        g_sigex[b*NCH + tid] = ss - s;
        g_gamex[b*NCH + tid] = gg - g;
    }
}

// ---------------- K3: chunk apply, 2 rows/thread ----------------
__global__ void __launch_bounds__(128) chunk_apply(
        const float* __restrict__ H, const float* __restrict__ MQ,
        int l, int fuse_next, float* Zoutp, float* LDJoutp) {
    __shared__ __align__(16) float4 Hs4[CHK*RSTRIDE];
    __shared__ __align__(16) float cp[Dn];
    __shared__ float zsh[CHK], csh[CHK], cshn[CHK], zo_sh[CHK];
    int blk = blockIdx.x;
    int base = blk * CHK;
    int tid = threadIdx.x;               // 128

    const float4* Hg4 = (const float4*)(H + (size_t)base*Dn);
    for (int i = tid; i < CHK*32; i += 128)
        Hs4[(i>>5)*RSTRIDE + (i&31)] = Hg4[i];
    if (tid < CHK) {
        zsh[tid] = g_Z[base + tid];
        csh[tid] = g_c[l*BS + base + tid];
        cshn[tid] = fuse_next ? g_c[(l+1)*BS + base + tid] : 0.f;
    }
    cp[tid] = g_Cex[blk*Dn + tid];
    __syncthreads();

    int pr = tid >> 2, p = tid & 3;
    int r0 = 2*pr, r1 = 2*pr + 1;
    int row0 = base + r0, row1 = base + r1;

    float4 hg0[8], hg1[8];
    const float4* hgr0 = (const float4*)(g_HG + (size_t)l*BS*Dn + (size_t)row0*Dn) + p;
    const float4* hgr1 = (const float4*)(g_HG + (size_t)l*BS*Dn + (size_t)row1*Dn) + p;
    #pragma unroll
    for (int q = 0; q < 8; q++) { hg0[q] = hgr0[q*4]; hg1[q] = hgr1[q*4]; }

    float a0 = g_a[l*BS + row0], a1 = g_a[l*BS + row1];
    float beta = g_beta[l];

    float cr0 = 0.f, cr1 = 0.f;
    const float4* cp4 = ((const float4*)cp) + p;
    #pragma unroll
    for (int q = 0; q < 8; q++) {
        float4 c4 = cp4[q*4];
        cr0 += hg0[q].x*c4.x + hg0[q].y*c4.y + hg0[q].z*c4.z + hg0[q].w*c4.w;
        cr1 += hg1[q].x*c4.x + hg1[q].y*c4.y + hg1[q].z*c4.z + hg1[q].w*c4.w;
    }

    float ip0 = 0.f, ip1 = 0.f, ds0 = 0.f, ds1 = 0.f;
    float szl0 = 0.f, scz0 = 0.f, szl1 = 0.f, scz1 = 0.f;
    int tmax = (r1 | 15) + 1;
    for (int t = 0; t < tmax; t++) {
        const float4* ht = Hs4 + t*RSTRIDE + p;
        float d0 = 0.f, d1 = 0.f;
        #pragma unroll
        for (int q = 0; q < 8; q++) {
            float4 h = ht[q*4];
            d0 += hg0[q].x*h.x + hg0[q].y*h.y + hg0[q].z*h.z + hg0[q].w*h.w;
            d1 += hg1[q].x*h.x + hg1[q].y*h.y + hg1[q].z*h.z + hg1[q].w*h.w;
        }
        float zt = zsh[t];
        if (t < r0)       ip0 += d0 * zt;
        else if (t == r0) ds0 = d0;
        if (t < r1)       ip1 += d1 * zt;
        else if (t == r1) ds1 = d1;
        if (p == 0) {
            float ct = csh[t];
            if (t < r0) { szl0 += zt; scz0 += ct*zt; }
            if (t < r1) { szl1 += zt; scz1 += ct*zt; }
        }
    }
    #pragma unroll
    for (int off = 1; off <= 2; off <<= 1) {
        ip0 += __shfl_xor_sync(0xffffffffu, ip0, off);
        ip1 += __shfl_xor_sync(0xffffffffu, ip1, off);
        ds0 += __shfl_xor_sync(0xffffffffu, ds0, off);
        ds1 += __shfl_xor_sync(0xffffffffu, ds1, off);
        cr0 += __shfl_xor_sync(0xffffffffu, cr0, off);
        cr1 += __shfl_xor_sync(0xffffffffu, cr1, off);
    }

    if (p == 0) {
        float sigp = g_sigex[blk], gamp = g_gamex[blk];
        const float E = 2.718281828459045f;
        #pragma unroll
        for (int rr = 0; rr < 2; rr++) {
            int r    = rr ? r1   : r0;
            int row  = rr ? row1 : row0;
            float as = rr ? a1   : a0;
            float crx = rr ? cr1 : cr0;
            float ipx = rr ? ip1 : ip0;
            float dsx = rr ? ds1 : ds0;
            float szl = rr ? szl1 : szl0;
            float scz = rr ? scz1 : scz0;

            float selfsc = SCALEF * (dsx + as + csh[r] + beta);
            float sp   = fmaxf(selfsc, 0.f) + log1pf(expf(-fabsf(selfsc)));
            float diag = sp + 1e-3f;
            float y = SCALEF*(crx + as*sigp + gamp + beta*sigp)
                    + SCALEF*(ipx + as*szl + scz + beta*szl)
                    + diag * zsh[r];

            float mq = MQ[row];
            float ldj = g_LDJ[row] + logf(diag) * mq;
            float th = g_theta[l*BS + row], ph = g_phi[l*BS + row];
            float z = y * mq * th + ph;
            ldj += th * mq;

            float zo, sl;
            if (fabsf(z) > 5.0f) {
                zo = z + (z > 0.f ? 1.f : -1.f);
                sl = 0.f;
            } else {
                float sh = sinhf(z);
                zo = asinhf(E * sh);
                float t1 = 1.f + E * sh;
                sl = logf(E * coshf(z)) - logf(t1 * t1);
            }
            ldj += sl * mq;

            zo_sh[r] = zo;
            if (Zoutp) { Zoutp[row] = zo; LDJoutp[row] = ldj; }
            else       { g_Z[row] = zo;   g_LDJ[row] = ldj; }
        }
    }

    if (fuse_next) {
        __syncthreads();
        const float* Hsf = (const float*)Hs4;
        float acc2 = 0.f;
        #pragma unroll 8
        for (int t = 0; t < CHK; t++) acc2 += Hsf[t*(RSTRIDE*4) + tid] * zo_sh[t];
        g_U[blk*Dn + tid] = acc2;
        if (tid == 127) {
            float ssum = 0.f, gsum = 0.f;
            for (int t = 0; t < CHK; t++) { ssum += zo_sh[t]; gsum += cshn[t]*zo_sh[t]; }
            g_sig[blk] = ssum; g_gam[blk] = gsum;
        }
    }
}

// ---------------- launch ----------------
extern "C" void kernel_launch(void* const* d_in, const int* in_sizes, int n_in,
                              void* d_out, int out_size) {
    (void)in_sizes; (void)n_in; (void)out_size;
    const float* H   = (const float*)d_in[0];
    const float* Y   = (const float*)d_in[1];
    const float* MQ  = (const float*)d_in[2];
    const float* Wq  = (const float*)d_in[3];
    const float* bq  = (const float*)d_in[4];
    const float* Wk  = (const float*)d_in[5];
    const float* bk  = (const float*)d_in[6];
    const float* tW1 = (const float*)d_in[7];
    const float* tb1 = (const float*)d_in[8];
    const float* tW2 = (const float*)d_in[9];
    const float* tb2 = (const float*)d_in[10];
    const float* pW1 = (const float*)d_in[11];
    const float* pb1 = (const float*)d_in[12];
    const float* pW2 = (const float*)d_in[13];
    const float* pb2 = (const float*)d_in[14];
    const float* wi  = (const float*)d_in[15];
    const float* bi  = (const float*)d_in[16];
    float* out = (float*)d_out;

    cudaFuncSetAttribute(gemm_mma, cudaFuncAttributeMaxDynamicSharedMemorySize,
                         GEMM_DYN_BYTES);

    // order: gemm_mma lands at ncu capture slot 6 (-s 5 -c 1)
    prep_G<<<dim3(Ln, Dn), Dn>>>(Wq, Wk, bq, bk);
    split_A<<<NTILE, 256>>>(H);
    prep_chunk<<<NCHUNK, 256>>>(H, Y, MQ, wi, bi);
    split_B<<<9, 256>>>(tW1, pW1);
    chunk_prefix<<<Bn, 128>>>();                 // layer-0 prefix
    gemm_mma<<<dim3(NTILE, 9), 256, GEMM_DYN_BYTES>>>(tb1, tW2, tb2, pb1, pW2, pb2);

    for (int l = 0; l < Ln; l++) {
        if (l > 0) chunk_prefix<<<Bn, 128>>>();
        if (l < Ln - 1) {
            chunk_apply<<<NCHUNK, 128>>>(H, MQ, l, 1, nullptr, nullptr);
        } else {
            chunk_apply<<<NCHUNK, 128>>>(H, MQ, l, 0, out, out + BS);
        }
    }
}

// round 8
// speedup vs baseline: 1.1375x; 1.0248x over previous
#include <cuda_runtime.h>
#include <cuda_bf16.h>
#include <math.h>
#include <stdint.h>

#define Bn 8
#define Sn 2048
#define Dn 128
#define Ln 3
#define BS (Bn*Sn)          // 16384 rows
#define CHK 64
#define NCH (Sn/CHK)        // 32
#define NCHUNK (Bn*NCH)     // 256
#define NTILE (BS/128)      // 128 row tiles
#define SCALEF 0.08838834764831845f
#define RSTRIDE 33          // padded smem row stride in float4

// bf16 image: 128 rows x 128 k, 256B row pitch, 16B-granule XOR swizzle
#define IMG_BYTES 32768
#define IMG_ELEMS 16384
#define STAGE_BYTES 65536                 // A split + B split
#define GEMM_DYN_BYTES (3*STAGE_BYTES)    // 192 KB

// ---------------- static device scratch ----------------
__device__ float g_G[Ln*Dn*Dn];
__device__ float g_u[Ln*Dn];
__device__ float g_v[Ln*Dn];
__device__ float g_beta[Ln];
__device__ float g_HG[Ln*BS*Dn];
__device__ float g_theta[Ln*BS];
__device__ float g_phi[Ln*BS];
__device__ float g_a[Ln*BS];
__device__ float g_c[Ln*BS];
__device__ float g_Z[BS];
__device__ float g_LDJ[BS];
__device__ float g_U[2][NCHUNK*Dn];      // double-buffered per layer parity
__device__ float g_sig[2][NCHUNK];
__device__ float g_gam[2][NCHUNK];
__device__ __align__(16) __nv_bfloat16 g_Abf[NTILE*3*IMG_ELEMS];  // 12.6 MB
__device__ __align__(16) __nv_bfloat16 g_Bbf[9*3*IMG_ELEMS];      // 884 KB

// ---------------- asm helpers ----------------
#define LDSM4(r0,r1,r2,r3, addr) \
    asm volatile("ldmatrix.sync.aligned.m8n8.x4.shared.b16 {%0,%1,%2,%3}, [%4];" \
        : "=r"(r0),"=r"(r1),"=r"(r2),"=r"(r3) : "r"(addr))

#define MMA_BF16(c, a, b) \
    asm volatile("mma.sync.aligned.m16n8k16.row.col.f32.bf16.bf16.f32 " \
        "{%0,%1,%2,%3},{%4,%5,%6,%7},{%8,%9},{%0,%1,%2,%3};" \
        : "+f"((c)[0]),"+f"((c)[1]),"+f"((c)[2]),"+f"((c)[3]) \
        : "r"((a)[0]),"r"((a)[1]),"r"((a)[2]),"r"((a)[3]), \
          "r"((b)[0]),"r"((b)[1]))

#define CP_ASYNC16(dst, src) \
    asm volatile("cp.async.cg.shared.global [%0], [%1], 16;" :: "r"(dst), "l"(src))
#define CP_COMMIT() asm volatile("cp.async.commit_group;" ::: "memory")
#define CP_WAIT(n)  asm volatile("cp.async.wait_group %0;" :: "n"(n) : "memory")

// ---------------- P0: G = Wq Wk^T, u, v, beta ----------------
__global__ void prep_G(const float* __restrict__ Wq, const float* __restrict__ Wk,
                       const float* __restrict__ bq, const float* __restrict__ bk) {
    int l = blockIdx.x;
    int drow = blockIdx.y;
    int e = threadIdx.x;            // 128 threads
    __shared__ float wq[Dn];
    wq[e] = Wq[l*Dn*Dn + drow*Dn + e];
    __syncthreads();
    const float* wkrow = Wk + l*Dn*Dn + e*Dn;
    float acc = 0.f;
    #pragma unroll 8
    for (int j = 0; j < Dn; j++) acc += wq[j] * wkrow[j];
    g_G[l*Dn*Dn + drow*Dn + e] = acc;
    if (e == 0) {
        float s = 0.f;
        const float* bkl = bk + l*Dn;
        for (int j = 0; j < Dn; j++) s += wq[j] * bkl[j];
        g_u[l*Dn + drow] = s;
    }
    if (drow == 0) {
        float s = 0.f;
        const float* bql = bq + l*Dn;
        for (int j = 0; j < Dn; j++) s += wkrow[j] * bql[j];
        g_v[l*Dn + e] = s;
        if (e == 0) {
            float sb = 0.f;
            for (int j = 0; j < Dn; j++) sb += bql[j] * bk[l*Dn + j];
            g_beta[l] = sb;
        }
    }
}

// ---------------- split helpers ----------------
__device__ __forceinline__ void bf3_split(float x, __nv_bfloat16& c0,
                                          __nv_bfloat16& c1, __nv_bfloat16& c2) {
    c0 = __float2bfloat16_rn(x);
    float r1 = x - __bfloat162float(c0);
    c1 = __float2bfloat16_rn(r1);
    float r2 = r1 - __bfloat162float(c1);
    c2 = __float2bfloat16_rn(r2);
}

// ldmatrix-friendly image: 256B row pitch, 16B granule XOR by (row&7)
__device__ __forceinline__ uint32_t img_off(int row, int g) {
    return (uint32_t)row*256u + (((uint32_t)g*16u) ^ (((uint32_t)row & 7u)*16u));
}

// ---------------- split_AB: H tiles + 9 weights -> 3x bf16 images ----------------
__global__ void __launch_bounds__(256) split_AB(const float* __restrict__ H,
                                                const float* __restrict__ tW1,
                                                const float* __restrict__ pW1) {
    int bx = blockIdx.x;
    int tid = threadIdx.x;
    if (bx < NTILE) {
        int tile = bx;
        char* basep = (char*)(g_Abf + (size_t)tile*3*IMG_ELEMS);
        for (int it = tid; it < 2048; it += 256) {
            int row = it >> 4, g = it & 15;   // granule = 8 k-elems
            const float4* src = (const float4*)(H + ((size_t)tile*128 + row)*Dn + g*8);
            float4 v0 = src[0], v1 = src[1];
            float x[8] = {v0.x,v0.y,v0.z,v0.w,v1.x,v1.y,v1.z,v1.w};
            __align__(16) __nv_bfloat16 b[3][8];
            #pragma unroll
            for (int e = 0; e < 8; e++) bf3_split(x[e], b[0][e], b[1][e], b[2][e]);
            uint32_t sw = img_off(row, g);
            #pragma unroll
            for (int s = 0; s < 3; s++)
                *(uint4*)(basep + s*IMG_BYTES + sw) = *(const uint4*)b[s];
        }
    } else {
        int w = bx - NTILE;          // 0..8
        int l = w / 3, kind = w - l*3;
        const float* W = (kind == 0) ? g_G + l*Dn*Dn
                       : (kind == 1) ? tW1 + l*Dn*Dn : pW1 + l*Dn*Dn;
        char* basep = (char*)(g_Bbf + (size_t)w*3*IMG_ELEMS);
        for (int it = tid; it < 2048; it += 256) {
            int g = it >> 7, n = it & 127;     // coalesced over n
            __align__(16) __nv_bfloat16 b[3][8];
            #pragma unroll
            for (int e = 0; e < 8; e++) {
                float xx = W[(size_t)(g*8 + e)*Dn + n];   // B[n][k] = W[k][n]
                bf3_split(xx, b[0][e], b[1][e], b[2][e]);
            }
            uint32_t sw = img_off(n, g);
            #pragma unroll
            for (int s = 0; s < 3; s++)
                *(uint4*)(basep + s*IMG_BYTES + sw) = *(const uint4*)b[s];
        }
    }
}

// ---------------- P1: fused per-row MVs + Z/LDJ init + layer-0 chunk sums ----------------
__global__ void __launch_bounds__(256) prep_chunk(
        const float* __restrict__ H, const float* __restrict__ Y,
        const float* __restrict__ MQ, const float* __restrict__ wi,
        const float* __restrict__ bi) {
    __shared__ __align__(16) float4 Hs4[CHK*RSTRIDE];
    __shared__ __align__(16) float sw[7*Dn];
    __shared__ float zsh[CHK], csh0[CHK];
    int blk = blockIdx.x;            // 256 chunks
    int base = blk * CHK;
    int tid = threadIdx.x;

    for (int i = tid; i < 7*Dn; i += 256)
        sw[i] = (i < Dn) ? wi[i] : (i < 4*Dn ? g_u[i-Dn] : g_v[i-4*Dn]);
    const float4* Hg4 = (const float4*)(H + (size_t)base*Dn);
    for (int i = tid; i < CHK*32; i += 256)
        Hs4[(i>>5)*RSTRIDE + (i&31)] = Hg4[i];
    __syncthreads();

    int r = tid >> 2, p = tid & 3;
    const float4* hrow = Hs4 + r*RSTRIDE + p;
    const float4* swp = ((const float4*)sw) + p;
    float acc[7];
    #pragma unroll
    for (int k = 0; k < 7; k++) acc[k] = 0.f;
    #pragma unroll
    for (int q = 0; q < 8; q++) {
        float4 h = hrow[q*4];
        #pragma unroll
        for (int k = 0; k < 7; k++) {
            float4 w = swp[k*32 + q*4];
            acc[k] += h.x*w.x + h.y*w.y + h.z*w.z + h.w*w.w;
        }
    }
    #pragma unroll
    for (int k = 0; k < 7; k++) {
        acc[k] += __shfl_xor_sync(0xffffffffu, acc[k], 1);
        acc[k] += __shfl_xor_sync(0xffffffffu, acc[k], 2);
    }
    int row = base + r;
    if (p == 0) {
        float el0 = acc[0] + bi[0];
        float y = Y[row], mq = MQ[row];
        float z = (y*mq - el0) * mq;
        g_Z[row] = z; zsh[r] = z;
        g_LDJ[row] = 1.0f;
        #pragma unroll
        for (int l = 0; l < Ln; l++) {
            g_a[l*BS + row] = acc[1+l];
            g_c[l*BS + row] = acc[4+l];
        }
        csh0[r] = acc[4];
    }
    __syncthreads();
    const float* Hsf = (const float*)Hs4;
    if (tid < Dn) {
        float a = 0.f;
        #pragma unroll 8
        for (int t = 0; t < CHK; t++) a += Hsf[t*(RSTRIDE*4) + tid] * zsh[t];
        g_U[0][blk*Dn + tid] = a;
    }
    if (tid == 255) {
        float s = 0.f, g = 0.f;
        for (int t = 0; t < CHK; t++) { s += zsh[t]; g += csh0[t]*zsh[t]; }
        g_sig[0][blk] = s; g_gam[0][blk] = g;
    }
}

// ---------------- P2: bf16x3 6-pass HMMA projection GEMM ----------------
// grid (NTILE, 9); 256 threads; warp tile 32x64; cp.async staged operands
__global__ void __launch_bounds__(256, 1) gemm_mma(
        const float* __restrict__ tb1, const float* __restrict__ tW2,
        const float* __restrict__ tb2, const float* __restrict__ pb1,
        const float* __restrict__ pW2, const float* __restrict__ pb2) {

    extern __shared__ __align__(16) char dynsm[];
    __shared__ float red[256];
    __shared__ float s_b1[128], s_w2[128];

    int tile = blockIdx.x, w = blockIdx.y;
    int l = w / 3, kind = w - l*3;
    int tid = threadIdx.x, lane = tid & 31, wid = tid >> 5;
    int wm = wid >> 1, wn = wid & 1;           // 4 x 2 warp grid
    int gid = lane >> 2, qid = lane & 3;

    uint32_t sbase = (uint32_t)__cvta_generic_to_shared(dynsm);

    // stage copies: stage s = [A split s 32KB | B split s 32KB]
    const char* srcA = (const char*)(g_Abf + (size_t)tile*3*IMG_ELEMS);
    const char* srcB = (const char*)(g_Bbf + (size_t)w*3*IMG_ELEMS);
    #pragma unroll
    for (int s = 0; s < 3; s++) {
        for (int i = tid; i < 4096; i += 256) {
            uint32_t dst = sbase + s*STAGE_BYTES + i*16;
            const char* src = (i < 2048) ? (srcA + s*IMG_BYTES + i*16)
                                         : (srcB + s*IMG_BYTES + (i-2048)*16);
            CP_ASYNC16(dst, src);
        }
        CP_COMMIT();
    }

    if (kind != 0 && tid < 128) {
        s_b1[tid] = ((kind == 1 ? tb1 : pb1) + l*Dn)[tid];
        s_w2[tid] = ((kind == 1 ? tW2 : pW2) + l*Dn)[tid];
    }

    // per-lane fragment address components
    uint32_t sw_l   = (lane & 7) * 16;
    uint32_t koffA  = (lane & 16);
    uint32_t koffB  = (lane & 8) << 1;
    uint32_t n_l    = (lane & 7) + ((lane & 16) >> 1);
    uint32_t a_mbase[2], b_nbase[4];
    #pragma unroll
    for (int mi = 0; mi < 2; mi++)
        a_mbase[mi] = (wm*32 + mi*16 + (lane & 15)) * 256;
    #pragma unroll
    for (int nbi = 0; nbi < 4; nbi++)
        b_nbase[nbi] = (wn*64 + nbi*16 + n_l) * 256;

    float c[2][8][4];
    #pragma unroll
    for (int mi = 0; mi < 2; mi++)
        #pragma unroll
        for (int ni = 0; ni < 8; ni++)
            #pragma unroll
            for (int j = 0; j < 4; j++) c[mi][ni][j] = 0.f;

    const int pi[6] = {0, 0, 1, 1, 0, 2};
    const int pj[6] = {0, 1, 0, 1, 2, 0};
    #pragma unroll
    for (int p = 0; p < 6; p++) {
        if (p == 0)      { CP_WAIT(2); __syncthreads(); }
        else if (p == 1) { CP_WAIT(1); __syncthreads(); }
        else if (p == 4) { CP_WAIT(0); __syncthreads(); }
        uint32_t aS = sbase + pi[p]*STAGE_BYTES;
        uint32_t bS = sbase + pj[p]*STAGE_BYTES + IMG_BYTES;
        #pragma unroll
        for (int kk = 0; kk < 8; kk++) {
            uint32_t af[2][4];
            #pragma unroll
            for (int mi = 0; mi < 2; mi++)
                LDSM4(af[mi][0], af[mi][1], af[mi][2], af[mi][3],
                      aS + a_mbase[mi] + ((kk*32u + koffA) ^ sw_l));
            uint32_t bf[8][2];
            #pragma unroll
            for (int nbi = 0; nbi < 4; nbi++)
                LDSM4(bf[2*nbi][0], bf[2*nbi][1], bf[2*nbi+1][0], bf[2*nbi+1][1],
                      bS + b_nbase[nbi] + ((kk*32u + koffB) ^ sw_l));
            #pragma unroll
            for (int mi = 0; mi < 2; mi++)
                #pragma unroll
                for (int ni = 0; ni < 8; ni++)
                    MMA_BF16(c[mi][ni], af[mi], bf[ni]);
        }
    }

    if (kind == 0) {
        float* outp = g_HG + (size_t)l*BS*Dn;
        #pragma unroll
        for (int mi = 0; mi < 2; mi++) {
            int r0 = tile*128 + wm*32 + mi*16 + gid;
            #pragma unroll
            for (int ni = 0; ni < 8; ni++) {
                int col = wn*64 + ni*8 + qid*2;
                *(float2*)(outp + (size_t)r0*Dn + col) =
                    make_float2(c[mi][ni][0], c[mi][ni][1]);
                *(float2*)(outp + (size_t)(r0+8)*Dn + col) =
                    make_float2(c[mi][ni][2], c[mi][ni][3]);
            }
        }
    } else {
        float pr[2][2] = {{0.f,0.f},{0.f,0.f}};
        #pragma unroll
        for (int ni = 0; ni < 8; ni++) {
            int col = wn*64 + ni*8 + qid*2;
            float b1a = s_b1[col], b1b = s_b1[col+1];
            float w2a = s_w2[col], w2b = s_w2[col+1];
            #pragma unroll
            for (int mi = 0; mi < 2; mi++) {
                pr[mi][0] += fmaxf(c[mi][ni][0]+b1a,0.f)*w2a
                           + fmaxf(c[mi][ni][1]+b1b,0.f)*w2b;
                pr[mi][1] += fmaxf(c[mi][ni][2]+b1a,0.f)*w2a
                           + fmaxf(c[mi][ni][3]+b1b,0.f)*w2b;
            }
        }
        #pragma unroll
        for (int mi = 0; mi < 2; mi++)
            #pragma unroll
            for (int hh = 0; hh < 2; hh++) {
                pr[mi][hh] += __shfl_xor_sync(0xffffffffu, pr[mi][hh], 1);
                pr[mi][hh] += __shfl_xor_sync(0xffffffffu, pr[mi][hh], 2);
            }
        if (qid == 0) {
            #pragma unroll
            for (int mi = 0; mi < 2; mi++)
                #pragma unroll
                for (int hh = 0; hh < 2; hh++)
                    red[(wm*32 + mi*16 + hh*8 + gid)*2 + wn] = pr[mi][hh];
        }
        __syncthreads();
        if (tid < 128) {
            float v = red[tid*2] + red[tid*2+1] + (kind == 1 ? tb2 : pb2)[l];
            float* outv = (kind == 1 ? g_theta : g_phi) + l*BS;
            outv[tile*128 + tid] = (kind == 1) ? expf(tanhf(v)) : v;
        }
    }
}

// ---------------- K3: chunk apply w/ inlined prefix, 2 rows/thread ----------------
__global__ void __launch_bounds__(128) chunk_apply(
        const float* __restrict__ H, const float* __restrict__ MQ,
        int l, int fuse_next, float* Zoutp, float* LDJoutp) {
    __shared__ __align__(16) float4 Hs4[CHK*RSTRIDE];
    __shared__ __align__(16) float cp[Dn];
    __shared__ float zsh[CHK], csh[CHK], cshn[CHK], zo_sh[CHK];
    __shared__ float s_sigp, s_gamp;
    int blk = blockIdx.x;
    int base = blk * CHK;
    int tid = threadIdx.x;               // 128
    int buf = l & 1, nbuf = buf ^ 1;
    int bb = blk / NCH, ch = blk - bb*NCH;

    // inlined exclusive prefix: sum U over chunks j < ch of this batch
    {
        const float* Ubase = &g_U[buf][(size_t)(bb*NCH)*Dn + tid];
        float accp = 0.f;
        #pragma unroll 8
        for (int j = 0; j < ch; j++) accp += Ubase[(size_t)j*Dn];
        cp[tid] = accp;
        if (tid < 32) {
            float sv = 0.f, gv = 0.f;
            if (tid < ch) {
                sv = g_sig[buf][bb*NCH + tid];
                gv = g_gam[buf][bb*NCH + tid];
            }
            #pragma unroll
            for (int off = 16; off > 0; off >>= 1) {
                sv += __shfl_xor_sync(0xffffffffu, sv, off);
                gv += __shfl_xor_sync(0xffffffffu, gv, off);
            }
            if (tid == 0) { s_sigp = sv; s_gamp = gv; }
        }
    }

    const float4* Hg4 = (const float4*)(H + (size_t)base*Dn);
    for (int i = tid; i < CHK*32; i += 128)
        Hs4[(i>>5)*RSTRIDE + (i&31)] = Hg4[i];
    if (tid < CHK) {
        zsh[tid] = g_Z[base + tid];
        csh[tid] = g_c[l*BS + base + tid];
        cshn[tid] = fuse_next ? g_c[(l+1)*BS + base + tid] : 0.f;
    }
    __syncthreads();

    int pr = tid >> 2, p = tid & 3;
    int r0 = 2*pr, r1 = 2*pr + 1;
    int row0 = base + r0, row1 = base + r1;

    float4 hg0[8], hg1[8];
    const float4* hgr0 = (const float4*)(g_HG + (size_t)l*BS*Dn + (size_t)row0*Dn) + p;
    const float4* hgr1 = (const float4*)(g_HG + (size_t)l*BS*Dn + (size_t)row1*Dn) + p;
    #pragma unroll
    for (int q = 0; q < 8; q++) { hg0[q] = hgr0[q*4]; hg1[q] = hgr1[q*4]; }

    float a0 = g_a[l*BS + row0], a1 = g_a[l*BS + row1];
    float beta = g_beta[l];

    float cr0 = 0.f, cr1 = 0.f;
    const float4* cp4 = ((const float4*)cp) + p;
    #pragma unroll
    for (int q = 0; q < 8; q++) {
        float4 c4 = cp4[q*4];
        cr0 += hg0[q].x*c4.x + hg0[q].y*c4.y + hg0[q].z*c4.z + hg0[q].w*c4.w;
        cr1 += hg1[q].x*c4.x + hg1[q].y*c4.y + hg1[q].z*c4.z + hg1[q].w*c4.w;
    }

    float ip0 = 0.f, ip1 = 0.f, ds0 = 0.f, ds1 = 0.f;
    float szl0 = 0.f, scz0 = 0.f, szl1 = 0.f, scz1 = 0.f;
    int tmax = (r1 | 15) + 1;
    for (int t = 0; t < tmax; t++) {
        const float4* ht = Hs4 + t*RSTRIDE + p;
        float d0 = 0.f, d1 = 0.f;
        #pragma unroll
        for (int q = 0; q < 8; q++) {
            float4 h = ht[q*4];
            d0 += hg0[q].x*h.x + hg0[q].y*h.y + hg0[q].z*h.z + hg0[q].w*h.w;
            d1 += hg1[q].x*h.x + hg1[q].y*h.y + hg1[q].z*h.z + hg1[q].w*h.w;
        }
        float zt = zsh[t];
        if (t < r0)       ip0 += d0 * zt;
        else if (t == r0) ds0 = d0;
        if (t < r1)       ip1 += d1 * zt;
        else if (t == r1) ds1 = d1;
        if (p == 0) {
            float ct = csh[t];
            if (t < r0) { szl0 += zt; scz0 += ct*zt; }
            if (t < r1) { szl1 += zt; scz1 += ct*zt; }
        }
    }
    #pragma unroll
    for (int off = 1; off <= 2; off <<= 1) {
        ip0 += __shfl_xor_sync(0xffffffffu, ip0, off);
        ip1 += __shfl_xor_sync(0xffffffffu, ip1, off);
        ds0 += __shfl_xor_sync(0xffffffffu, ds0, off);
        ds1 += __shfl_xor_sync(0xffffffffu, ds1, off);
        cr0 += __shfl_xor_sync(0xffffffffu, cr0, off);
        cr1 += __shfl_xor_sync(0xffffffffu, cr1, off);
    }

    if (p == 0) {
        float sigp = s_sigp, gamp = s_gamp;
        const float E = 2.718281828459045f;
        #pragma unroll
        for (int rr = 0; rr < 2; rr++) {
            int r    = rr ? r1   : r0;
            int row  = rr ? row1 : row0;
            float as = rr ? a1   : a0;
            float crx = rr ? cr1 : cr0;
            float ipx = rr ? ip1 : ip0;
            float dsx = rr ? ds1 : ds0;
            float szl = rr ? szl1 : szl0;
            float scz = rr ? scz1 : scz0;

            float selfsc = SCALEF * (dsx + as + csh[r] + beta);
            float sp   = fmaxf(selfsc, 0.f) + log1pf(expf(-fabsf(selfsc)));
            float diag = sp + 1e-3f;
            float y = SCALEF*(crx + as*sigp + gamp + beta*sigp)
                    + SCALEF*(ipx + as*szl + scz + beta*szl)
                    + diag * zsh[r];

            float mq = MQ[row];
            float ldj = g_LDJ[row] + logf(diag) * mq;
            float th = g_theta[l*BS + row], ph = g_phi[l*BS + row];
            float z = y * mq * th + ph;
            ldj += th * mq;

            float zo, sl;
            if (fabsf(z) > 5.0f) {
                zo = z + (z > 0.f ? 1.f : -1.f);
                sl = 0.f;
            } else {
                float sh = sinhf(z);
                zo = asinhf(E * sh);
                float t1 = 1.f + E * sh;
                sl = logf(E * coshf(z)) - logf(t1 * t1);
            }
            ldj += sl * mq;

            zo_sh[r] = zo;
            if (Zoutp) { Zoutp[row] = zo; LDJoutp[row] = ldj; }
            else       { g_Z[row] = zo;   g_LDJ[row] = ldj; }
        }
    }

    if (fuse_next) {
        __syncthreads();
        const float* Hsf = (const float*)Hs4;
        float acc2 = 0.f;
        #pragma unroll 8
        for (int t = 0; t < CHK; t++) acc2 += Hsf[t*(RSTRIDE*4) + tid] * zo_sh[t];
        g_U[nbuf][blk*Dn + tid] = acc2;
        if (tid == 127) {
            float ssum = 0.f, gsum = 0.f;
            for (int t = 0; t < CHK; t++) { ssum += zo_sh[t]; gsum += cshn[t]*zo_sh[t]; }
            g_sig[nbuf][blk] = ssum; g_gam[nbuf][blk] = gsum;
        }
    }
}

// ---------------- launch ----------------
extern "C" void kernel_launch(void* const* d_in, const int* in_sizes, int n_in,
                              void* d_out, int out_size) {
    (void)in_sizes; (void)n_in; (void)out_size;
    const float* H   = (const float*)d_in[0];
    const float* Y   = (const float*)d_in[1];
    const float* MQ  = (const float*)d_in[2];
    const float* Wq  = (const float*)d_in[3];
    const float* bq  = (const float*)d_in[4];
    const float* Wk  = (const float*)d_in[5];
    const float* bk  = (const float*)d_in[6];
    const float* tW1 = (const float*)d_in[7];
    const float* tb1 = (const float*)d_in[8];
    const float* tW2 = (const float*)d_in[9];
    const float* tb2 = (const float*)d_in[10];
    const float* pW1 = (const float*)d_in[11];
    const float* pb1 = (const float*)d_in[12];
    const float* pW2 = (const float*)d_in[13];
    const float* pb2 = (const float*)d_in[14];
    const float* wi  = (const float*)d_in[15];
    const float* bi  = (const float*)d_in[16];
    float* out = (float*)d_out;

    cudaFuncSetAttribute(gemm_mma, cudaFuncAttributeMaxDynamicSharedMemorySize,
                         GEMM_DYN_BYTES);

    // launch #4 = gemm_mma (the profiled slot)
    prep_G<<<dim3(Ln, Dn), Dn>>>(Wq, Wk, bq, bk);
    split_AB<<<NTILE + 9, 256>>>(H, tW1, pW1);
    prep_chunk<<<NCHUNK, 256>>>(H, Y, MQ, wi, bi);
    gemm_mma<<<dim3(NTILE, 9), 256, GEMM_DYN_BYTES>>>(tb1, tW2, tb2, pb1, pW2, pb2);

    for (int l = 0; l < Ln; l++) {
        if (l < Ln - 1) {
            chunk_apply<<<NCHUNK, 128>>>(H, MQ, l, 1, nullptr, nullptr);
        } else {
            chunk_apply<<<NCHUNK, 128>>>(H, MQ, l, 0, out, out + BS);
        }
    }
}